// round 2
// baseline (speedup 1.0000x reference)
#include <cuda_runtime.h>
#include <cuda_bf16.h>
#include <math.h>

// ---------------------------------------------------------------------------
// GroupedQueryAttention: x->QKV GEMM -> RoPE -> doc-masked causal flash attn
// -> output GEMM.  fp32 baseline (Round 0).
// B=2, T=2048, D_MODEL=2048, H=16, KVH=4, HEAD_DIM=128
// ---------------------------------------------------------------------------

#define BATCH 2
#define SEQ 2048
#define DMODEL 2048
#define NHEADS 16
#define NKV 4
#define HDIM 128
#define KVDIM (NKV * HDIM)        // 512
#define QKVN (DMODEL + 2 * KVDIM) // 3072
#define BT (BATCH * SEQ)          // 4096
#define ATT_SCALE 0.08838834764831845f

// ---- scratch (device globals: allocation is forbidden) --------------------
__device__ float g_qkv[BT * QKVN];                   // 12.6M floats
__device__ float g_q[BATCH * NHEADS * SEQ * HDIM];   // 8.4M
__device__ float g_k[BATCH * NKV * SEQ * HDIM];      // 2.1M
__device__ float g_v[BATCH * NKV * SEQ * HDIM];      // 2.1M
__device__ float g_att[BT * DMODEL];                 // 8.4M
__device__ int   g_dstart[BT];

// ---------------------------------------------------------------------------
// SGEMM: C[M,N] = A[M,K] * B[K,N], all row-major, M%128==0, N%128==0, K%16==0
// 128x128 block tile, 16 k-slice, 8x8 per-thread, 256 threads.
// ---------------------------------------------------------------------------
__global__ __launch_bounds__(256) void sgemm128(
    const float* __restrict__ A, const float* __restrict__ B,
    float* __restrict__ C, int M, int N, int K)
{
    __shared__ float As[16][128];   // [k][m] (transposed on load)
    __shared__ float Bs[16][128];   // [k][n]

    const int tid = threadIdx.x;
    const int tx = tid & 15;        // n-dir
    const int ty = tid >> 4;        // m-dir
    const int m0 = blockIdx.y * 128;
    const int n0 = blockIdx.x * 128;

    float acc[8][8];
#pragma unroll
    for (int i = 0; i < 8; i++)
#pragma unroll
        for (int j = 0; j < 8; j++) acc[i][j] = 0.0f;

    for (int kt = 0; kt < K; kt += 16) {
#pragma unroll
        for (int it = 0; it < 2; it++) {
            int id = tid + it * 256;          // 0..511 float4 slots
            // A tile: 128 rows x 16 cols
            int ar = id >> 2;                 // 0..127
            int ac = (id & 3) << 2;           // 0,4,8,12
            float4 av = *(const float4*)(A + (size_t)(m0 + ar) * K + kt + ac);
            As[ac + 0][ar] = av.x;
            As[ac + 1][ar] = av.y;
            As[ac + 2][ar] = av.z;
            As[ac + 3][ar] = av.w;
            // B tile: 16 rows x 128 cols
            int br = id >> 5;                 // 0..15
            int bc = (id & 31) << 2;          // 0..124
            *(float4*)&Bs[br][bc] =
                *(const float4*)(B + (size_t)(kt + br) * N + n0 + bc);
        }
        __syncthreads();

#pragma unroll
        for (int kk = 0; kk < 16; kk++) {
            float a[8], b[8];
            *(float4*)&a[0] = *(float4*)&As[kk][ty * 8];
            *(float4*)&a[4] = *(float4*)&As[kk][ty * 8 + 4];
            *(float4*)&b[0] = *(float4*)&Bs[kk][tx * 8];
            *(float4*)&b[4] = *(float4*)&Bs[kk][tx * 8 + 4];
#pragma unroll
            for (int i = 0; i < 8; i++)
#pragma unroll
                for (int j = 0; j < 8; j++)
                    acc[i][j] = fmaf(a[i], b[j], acc[i][j]);
        }
        __syncthreads();
    }

#pragma unroll
    for (int i = 0; i < 8; i++) {
        float* crow = C + (size_t)(m0 + ty * 8 + i) * N + n0 + tx * 8;
        *(float4*)crow       = make_float4(acc[i][0], acc[i][1], acc[i][2], acc[i][3]);
        *(float4*)(crow + 4) = make_float4(acc[i][4], acc[i][5], acc[i][6], acc[i][7]);
    }
}

// ---------------------------------------------------------------------------
// RoPE + reorder: qkv[bt][3072] -> Q[b][h][t][128] (roped),
//                 K[b][g][t][128] (roped), V[b][g][t][128]
// 1536 work units per (b,t): 1024 q-pairs, 256 k-pairs, 256 v-pairs
// ---------------------------------------------------------------------------
__global__ __launch_bounds__(256) void rope_reorder(
    const float* __restrict__ qkv, const float* __restrict__ S,
    const float* __restrict__ C, float* __restrict__ Q,
    float* __restrict__ Kd, float* __restrict__ Vd)
{
    int idx = blockIdx.x * blockDim.x + threadIdx.x;
    int u = idx % 1536;
    int bt = idx / 1536;
    int b = bt >> 11;
    int t = bt & 2047;
    const float* src = qkv + (size_t)bt * QKVN;
    int d = u & 63;
    float s = S[t * 64 + d];
    float c = C[t * 64 + d];

    if (u < 1024) {
        int h = u >> 6;
        float x1 = src[h * HDIM + d];
        float x2 = src[h * HDIM + d + 64];
        float* dst = Q + ((size_t)(b * NHEADS + h) * SEQ + t) * HDIM;
        dst[d] = x1 * c - x2 * s;
        dst[d + 64] = x2 * c + x1 * s;
    } else if (u < 1280) {
        int h = (u - 1024) >> 6;
        float x1 = src[DMODEL + h * HDIM + d];
        float x2 = src[DMODEL + h * HDIM + d + 64];
        float* dst = Kd + ((size_t)(b * NKV + h) * SEQ + t) * HDIM;
        dst[d] = x1 * c - x2 * s;
        dst[d + 64] = x2 * c + x1 * s;
    } else {
        int h = (u - 1280) >> 6;
        float* dst = Vd + ((size_t)(b * NKV + h) * SEQ + t) * HDIM;
        dst[d] = src[DMODEL + KVDIM + h * HDIM + d];
        dst[d + 64] = src[DMODEL + KVDIM + h * HDIM + d + 64];
    }
}

// ---------------------------------------------------------------------------
// doc_start: first index of the query's doc (doc_ids sorted ascending per b)
// ---------------------------------------------------------------------------
__global__ void docstart_kernel(const int* __restrict__ doc, int* __restrict__ ds)
{
    int i = blockIdx.x * blockDim.x + threadIdx.x;
    if (i >= BT) return;
    int b = i >> 11;
    int t = i & 2047;
    const int* row = doc + b * SEQ;
    int my = row[t];
    int lo = 0, hi = t;
    while (lo < hi) {
        int mid = (lo + hi) >> 1;
        if (row[mid] == my) hi = mid;
        else lo = mid + 1;
    }
    ds[i] = lo;
}

// ---------------------------------------------------------------------------
// Flash attention, fp32. Q tile 64 rows x 128d, K/V tiles 64 x 128.
// Only iterates k-tiles in [doc_start(t0) .. t0] (doc-range mask).
// 256 threads: ty=tid/16 owns q-rows 4ty..4ty+3; tx=tid%16 owns
// score-cols 4tx..4tx+3 (S phase) and out-dims 8tx..8tx+7 (PV phase).
// Dynamic smem layout (floats):
//   Qs[128][68] (d-major), Ks[128][68] (d-major), Vs[64][128], Ps[64][68]
// ---------------------------------------------------------------------------
#define QS_OFF 0
#define KS_OFF (128 * 68)
#define VS_OFF (2 * 128 * 68)
#define PS_OFF (2 * 128 * 68 + 64 * 128)
#define FA_SMEM_FLOATS (2 * 128 * 68 + 64 * 128 + 64 * 68)
#define FA_SMEM_BYTES (FA_SMEM_FLOATS * 4)

__global__ __launch_bounds__(256) void flash_kernel(
    const float* __restrict__ Q, const float* __restrict__ Kg,
    const float* __restrict__ Vg, const int* __restrict__ dstart,
    float* __restrict__ Out)
{
    extern __shared__ float sm[];
    float* Qs = sm + QS_OFF;
    float* Ks = sm + KS_OFF;
    float* Vs = sm + VS_OFF;
    float* Ps = sm + PS_OFF;

    const int t0 = blockIdx.x * 64;
    const int h  = blockIdx.y;
    const int b  = blockIdx.z;
    const int g  = h >> 2;
    const int tid = threadIdx.x;
    const int tx = tid & 15;
    const int ty = tid >> 4;
    const int r0 = ty * 4;
    const int c0 = tx * 4;
    const int d0 = tx * 8;

    const float* Qbase = Q + ((size_t)(b * NHEADS + h) * SEQ + t0) * HDIM;
    const float* Kbase = Kg + (size_t)(b * NKV + g) * SEQ * HDIM;
    const float* Vbase = Vg + (size_t)(b * NKV + g) * SEQ * HDIM;

    // load Q tile transposed (d-major)
#pragma unroll
    for (int it = 0; it < 8; it++) {
        int id = tid + it * 256;          // 0..2047 float4 slots
        int r = id >> 5;                  // 0..63
        int c4 = (id & 31) << 2;          // 0..124
        float4 v = *(const float4*)(Qbase + (size_t)r * HDIM + c4);
        Qs[(c4 + 0) * 68 + r] = v.x;
        Qs[(c4 + 1) * 68 + r] = v.y;
        Qs[(c4 + 2) * 68 + r] = v.z;
        Qs[(c4 + 3) * 68 + r] = v.w;
    }

    int ds[4];
#pragma unroll
    for (int i = 0; i < 4; i++) ds[i] = dstart[b * SEQ + t0 + r0 + i];
    const int kt0 = (dstart[b * SEQ + t0] >> 6) << 6;

    float m[4], l[4], O[4][8];
#pragma unroll
    for (int i = 0; i < 4; i++) {
        m[i] = -INFINITY;
        l[i] = 0.0f;
#pragma unroll
        for (int j = 0; j < 8; j++) O[i][j] = 0.0f;
    }

    __syncthreads();

    for (int kt = kt0; kt <= t0; kt += 64) {
        // load K (d-major) and V (natural) tiles
#pragma unroll
        for (int it = 0; it < 8; it++) {
            int id = tid + it * 256;
            int r = id >> 5;
            int c4 = (id & 31) << 2;
            float4 kv = *(const float4*)(Kbase + (size_t)(kt + r) * HDIM + c4);
            Ks[(c4 + 0) * 68 + r] = kv.x;
            Ks[(c4 + 1) * 68 + r] = kv.y;
            Ks[(c4 + 2) * 68 + r] = kv.z;
            Ks[(c4 + 3) * 68 + r] = kv.w;
            float4 vv = *(const float4*)(Vbase + (size_t)(kt + r) * HDIM + c4);
            *(float4*)&Vs[r * HDIM + c4] = vv;
        }
        __syncthreads();

        // S = Q K^T  (4x4 per thread)
        float s[4][4];
#pragma unroll
        for (int i = 0; i < 4; i++)
#pragma unroll
            for (int j = 0; j < 4; j++) s[i][j] = 0.0f;

#pragma unroll 4
        for (int d = 0; d < HDIM; d++) {
            float4 a = *(float4*)&Qs[d * 68 + r0];
            float4 kb = *(float4*)&Ks[d * 68 + c0];
            float av[4] = {a.x, a.y, a.z, a.w};
            float bv[4] = {kb.x, kb.y, kb.z, kb.w};
#pragma unroll
            for (int i = 0; i < 4; i++)
#pragma unroll
                for (int j = 0; j < 4; j++)
                    s[i][j] = fmaf(av[i], bv[j], s[i][j]);
        }

        // mask + scale
#pragma unroll
        for (int i = 0; i < 4; i++) {
            int qi = t0 + r0 + i;
#pragma unroll
            for (int j = 0; j < 4; j++) {
                int kj = kt + c0 + j;
                bool ok = (kj <= qi) && (kj >= ds[i]);
                s[i][j] = ok ? s[i][j] * ATT_SCALE : -1.0e30f;
            }
        }

        // online softmax update per q-row
#pragma unroll
        for (int i = 0; i < 4; i++) {
            float mx = fmaxf(fmaxf(s[i][0], s[i][1]), fmaxf(s[i][2], s[i][3]));
#pragma unroll
            for (int off = 8; off >= 1; off >>= 1)
                mx = fmaxf(mx, __shfl_xor_sync(0xffffffffu, mx, off));
            float mnew = fmaxf(m[i], mx);
            float corr = __expf(m[i] - mnew);
            float p[4];
            float psum = 0.0f;
#pragma unroll
            for (int j = 0; j < 4; j++) {
                float pv = __expf(s[i][j] - mnew);
                if (s[i][j] < -1.0e29f) pv = 0.0f;
                p[j] = pv;
                psum += pv;
            }
#pragma unroll
            for (int off = 8; off >= 1; off >>= 1)
                psum += __shfl_xor_sync(0xffffffffu, psum, off);
            l[i] = l[i] * corr + psum;
            m[i] = mnew;
#pragma unroll
            for (int j = 0; j < 8; j++) O[i][j] *= corr;
            *(float4*)&Ps[(r0 + i) * 68 + c0] = make_float4(p[0], p[1], p[2], p[3]);
        }
        __syncthreads();

        // O += P @ V
#pragma unroll 2
        for (int c = 0; c < 64; c++) {
            float p0 = Ps[(r0 + 0) * 68 + c];
            float p1 = Ps[(r0 + 1) * 68 + c];
            float p2 = Ps[(r0 + 2) * 68 + c];
            float p3 = Ps[(r0 + 3) * 68 + c];
            float4 v0 = *(float4*)&Vs[c * HDIM + d0];
            float4 v1 = *(float4*)&Vs[c * HDIM + d0 + 4];
            float vv[8] = {v0.x, v0.y, v0.z, v0.w, v1.x, v1.y, v1.z, v1.w};
#pragma unroll
            for (int j = 0; j < 8; j++) {
                O[0][j] = fmaf(p0, vv[j], O[0][j]);
                O[1][j] = fmaf(p1, vv[j], O[1][j]);
                O[2][j] = fmaf(p2, vv[j], O[2][j]);
                O[3][j] = fmaf(p3, vv[j], O[3][j]);
            }
        }
        __syncthreads();
    }

    // normalize + write: out[b][t][h*128 + d]
#pragma unroll
    for (int i = 0; i < 4; i++) {
        float inv = 1.0f / l[i];
        float* orow = Out + ((size_t)b * SEQ + t0 + r0 + i) * DMODEL + h * HDIM + d0;
        *(float4*)orow =
            make_float4(O[i][0] * inv, O[i][1] * inv, O[i][2] * inv, O[i][3] * inv);
        *(float4*)(orow + 4) =
            make_float4(O[i][4] * inv, O[i][5] * inv, O[i][6] * inv, O[i][7] * inv);
    }
}

// ---------------------------------------------------------------------------
extern "C" void kernel_launch(void* const* d_in, const int* in_sizes, int n_in,
                              void* d_out, int out_size)
{
    const float* x    = (const float*)d_in[0];
    const float* sinp = (const float*)d_in[1];
    const float* cosp = (const float*)d_in[2];
    const int*   doc  = (const int*)d_in[3];
    const float* wqkv = (const float*)d_in[4];
    const float* wo   = (const float*)d_in[5];
    float* out = (float*)d_out;

    float *qkv, *q, *k, *v, *att;
    int* dstart;
    cudaGetSymbolAddress((void**)&qkv, g_qkv);
    cudaGetSymbolAddress((void**)&q, g_q);
    cudaGetSymbolAddress((void**)&k, g_k);
    cudaGetSymbolAddress((void**)&v, g_v);
    cudaGetSymbolAddress((void**)&att, g_att);
    cudaGetSymbolAddress((void**)&dstart, g_dstart);

    // 1) QKV projection: [4096,2048] @ [2048,3072]
    sgemm128<<<dim3(QKVN / 128, BT / 128), 256>>>(x, wqkv, qkv, BT, QKVN, DMODEL);

    // 2) RoPE + reorder
    rope_reorder<<<(BT * 1536) / 256, 256>>>(qkv, sinp, cosp, q, k, v);

    // 3) doc starts
    docstart_kernel<<<BT / 256, 256>>>(doc, dstart);

    // 4) flash attention
    cudaFuncSetAttribute(flash_kernel,
                         cudaFuncAttributeMaxDynamicSharedMemorySize,
                         FA_SMEM_BYTES);
    flash_kernel<<<dim3(SEQ / 64, NHEADS, BATCH), 256, FA_SMEM_BYTES>>>(
        q, k, v, dstart, att);

    // 5) output projection: [4096,2048] @ [2048,2048]
    sgemm128<<<dim3(DMODEL / 128, BT / 128), 256>>>(att, wo, out, BT, DMODEL, DMODEL);
}

// round 3
// speedup vs baseline: 1.0004x; 1.0004x over previous
#include <cuda_runtime.h>
#include <cuda_bf16.h>
#include <math.h>

// ---------------------------------------------------------------------------
// GroupedQueryAttention: x->QKV GEMM -> RoPE -> doc-masked causal flash attn
// -> output GEMM.  fp32 baseline (Round 0).
// B=2, T=2048, D_MODEL=2048, H=16, KVH=4, HEAD_DIM=128
// ---------------------------------------------------------------------------

#define BATCH 2
#define SEQ 2048
#define DMODEL 2048
#define NHEADS 16
#define NKV 4
#define HDIM 128
#define KVDIM (NKV * HDIM)        // 512
#define QKVN (DMODEL + 2 * KVDIM) // 3072
#define BT (BATCH * SEQ)          // 4096
#define ATT_SCALE 0.08838834764831845f

// ---- scratch (device globals: allocation is forbidden) --------------------
__device__ float g_qkv[BT * QKVN];                   // 12.6M floats
__device__ float g_q[BATCH * NHEADS * SEQ * HDIM];   // 8.4M
__device__ float g_k[BATCH * NKV * SEQ * HDIM];      // 2.1M
__device__ float g_v[BATCH * NKV * SEQ * HDIM];      // 2.1M
__device__ float g_att[BT * DMODEL];                 // 8.4M
__device__ int   g_dstart[BT];

// ---------------------------------------------------------------------------
// SGEMM: C[M,N] = A[M,K] * B[K,N], all row-major, M%128==0, N%128==0, K%16==0
// 128x128 block tile, 16 k-slice, 8x8 per-thread, 256 threads.
// ---------------------------------------------------------------------------
__global__ __launch_bounds__(256) void sgemm128(
    const float* __restrict__ A, const float* __restrict__ B,
    float* __restrict__ C, int M, int N, int K)
{
    __shared__ float As[16][128];   // [k][m] (transposed on load)
    __shared__ float Bs[16][128];   // [k][n]

    const int tid = threadIdx.x;
    const int tx = tid & 15;        // n-dir
    const int ty = tid >> 4;        // m-dir
    const int m0 = blockIdx.y * 128;
    const int n0 = blockIdx.x * 128;

    float acc[8][8];
#pragma unroll
    for (int i = 0; i < 8; i++)
#pragma unroll
        for (int j = 0; j < 8; j++) acc[i][j] = 0.0f;

    for (int kt = 0; kt < K; kt += 16) {
#pragma unroll
        for (int it = 0; it < 2; it++) {
            int id = tid + it * 256;          // 0..511 float4 slots
            // A tile: 128 rows x 16 cols
            int ar = id >> 2;                 // 0..127
            int ac = (id & 3) << 2;           // 0,4,8,12
            float4 av = *(const float4*)(A + (size_t)(m0 + ar) * K + kt + ac);
            As[ac + 0][ar] = av.x;
            As[ac + 1][ar] = av.y;
            As[ac + 2][ar] = av.z;
            As[ac + 3][ar] = av.w;
            // B tile: 16 rows x 128 cols
            int br = id >> 5;                 // 0..15
            int bc = (id & 31) << 2;          // 0..124
            *(float4*)&Bs[br][bc] =
                *(const float4*)(B + (size_t)(kt + br) * N + n0 + bc);
        }
        __syncthreads();

#pragma unroll
        for (int kk = 0; kk < 16; kk++) {
            float a[8], b[8];
            *(float4*)&a[0] = *(float4*)&As[kk][ty * 8];
            *(float4*)&a[4] = *(float4*)&As[kk][ty * 8 + 4];
            *(float4*)&b[0] = *(float4*)&Bs[kk][tx * 8];
            *(float4*)&b[4] = *(float4*)&Bs[kk][tx * 8 + 4];
#pragma unroll
            for (int i = 0; i < 8; i++)
#pragma unroll
                for (int j = 0; j < 8; j++)
                    acc[i][j] = fmaf(a[i], b[j], acc[i][j]);
        }
        __syncthreads();
    }

#pragma unroll
    for (int i = 0; i < 8; i++) {
        float* crow = C + (size_t)(m0 + ty * 8 + i) * N + n0 + tx * 8;
        *(float4*)crow       = make_float4(acc[i][0], acc[i][1], acc[i][2], acc[i][3]);
        *(float4*)(crow + 4) = make_float4(acc[i][4], acc[i][5], acc[i][6], acc[i][7]);
    }
}

// ---------------------------------------------------------------------------
// RoPE + reorder: qkv[bt][3072] -> Q[b][h][t][128] (roped),
//                 K[b][g][t][128] (roped), V[b][g][t][128]
// 1536 work units per (b,t): 1024 q-pairs, 256 k-pairs, 256 v-pairs
// ---------------------------------------------------------------------------
__global__ __launch_bounds__(256) void rope_reorder(
    const float* __restrict__ qkv, const float* __restrict__ S,
    const float* __restrict__ C, float* __restrict__ Q,
    float* __restrict__ Kd, float* __restrict__ Vd)
{
    int idx = blockIdx.x * blockDim.x + threadIdx.x;
    int u = idx % 1536;
    int bt = idx / 1536;
    int b = bt >> 11;
    int t = bt & 2047;
    const float* src = qkv + (size_t)bt * QKVN;
    int d = u & 63;
    float s = S[t * 64 + d];
    float c = C[t * 64 + d];

    if (u < 1024) {
        int h = u >> 6;
        float x1 = src[h * HDIM + d];
        float x2 = src[h * HDIM + d + 64];
        float* dst = Q + ((size_t)(b * NHEADS + h) * SEQ + t) * HDIM;
        dst[d] = x1 * c - x2 * s;
        dst[d + 64] = x2 * c + x1 * s;
    } else if (u < 1280) {
        int h = (u - 1024) >> 6;
        float x1 = src[DMODEL + h * HDIM + d];
        float x2 = src[DMODEL + h * HDIM + d + 64];
        float* dst = Kd + ((size_t)(b * NKV + h) * SEQ + t) * HDIM;
        dst[d] = x1 * c - x2 * s;
        dst[d + 64] = x2 * c + x1 * s;
    } else {
        int h = (u - 1280) >> 6;
        float* dst = Vd + ((size_t)(b * NKV + h) * SEQ + t) * HDIM;
        dst[d] = src[DMODEL + KVDIM + h * HDIM + d];
        dst[d + 64] = src[DMODEL + KVDIM + h * HDIM + d + 64];
    }
}

// ---------------------------------------------------------------------------
// doc_start: first index of the query's doc (doc_ids sorted ascending per b)
// ---------------------------------------------------------------------------
__global__ void docstart_kernel(const int* __restrict__ doc, int* __restrict__ ds)
{
    int i = blockIdx.x * blockDim.x + threadIdx.x;
    if (i >= BT) return;
    int b = i >> 11;
    int t = i & 2047;
    const int* row = doc + b * SEQ;
    int my = row[t];
    int lo = 0, hi = t;
    while (lo < hi) {
        int mid = (lo + hi) >> 1;
        if (row[mid] == my) hi = mid;
        else lo = mid + 1;
    }
    ds[i] = lo;
}

// ---------------------------------------------------------------------------
// Flash attention, fp32. Q tile 64 rows x 128d, K/V tiles 64 x 128.
// Only iterates k-tiles in [doc_start(t0) .. t0] (doc-range mask).
// 256 threads: ty=tid/16 owns q-rows 4ty..4ty+3; tx=tid%16 owns
// score-cols 4tx..4tx+3 (S phase) and out-dims 8tx..8tx+7 (PV phase).
// Dynamic smem layout (floats):
//   Qs[128][68] (d-major), Ks[128][68] (d-major), Vs[64][128], Ps[64][68]
// ---------------------------------------------------------------------------
#define QS_OFF 0
#define KS_OFF (128 * 68)
#define VS_OFF (2 * 128 * 68)
#define PS_OFF (2 * 128 * 68 + 64 * 128)
#define FA_SMEM_FLOATS (2 * 128 * 68 + 64 * 128 + 64 * 68)
#define FA_SMEM_BYTES (FA_SMEM_FLOATS * 4)

__global__ __launch_bounds__(256) void flash_kernel(
    const float* __restrict__ Q, const float* __restrict__ Kg,
    const float* __restrict__ Vg, const int* __restrict__ dstart,
    float* __restrict__ Out)
{
    extern __shared__ float sm[];
    float* Qs = sm + QS_OFF;
    float* Ks = sm + KS_OFF;
    float* Vs = sm + VS_OFF;
    float* Ps = sm + PS_OFF;

    const int t0 = blockIdx.x * 64;
    const int h  = blockIdx.y;
    const int b  = blockIdx.z;
    const int g  = h >> 2;
    const int tid = threadIdx.x;
    const int tx = tid & 15;
    const int ty = tid >> 4;
    const int r0 = ty * 4;
    const int c0 = tx * 4;
    const int d0 = tx * 8;

    const float* Qbase = Q + ((size_t)(b * NHEADS + h) * SEQ + t0) * HDIM;
    const float* Kbase = Kg + (size_t)(b * NKV + g) * SEQ * HDIM;
    const float* Vbase = Vg + (size_t)(b * NKV + g) * SEQ * HDIM;

    // load Q tile transposed (d-major)
#pragma unroll
    for (int it = 0; it < 8; it++) {
        int id = tid + it * 256;          // 0..2047 float4 slots
        int r = id >> 5;                  // 0..63
        int c4 = (id & 31) << 2;          // 0..124
        float4 v = *(const float4*)(Qbase + (size_t)r * HDIM + c4);
        Qs[(c4 + 0) * 68 + r] = v.x;
        Qs[(c4 + 1) * 68 + r] = v.y;
        Qs[(c4 + 2) * 68 + r] = v.z;
        Qs[(c4 + 3) * 68 + r] = v.w;
    }

    int ds[4];
#pragma unroll
    for (int i = 0; i < 4; i++) ds[i] = dstart[b * SEQ + t0 + r0 + i];
    const int kt0 = (dstart[b * SEQ + t0] >> 6) << 6;

    float m[4], l[4], O[4][8];
#pragma unroll
    for (int i = 0; i < 4; i++) {
        m[i] = -INFINITY;
        l[i] = 0.0f;
#pragma unroll
        for (int j = 0; j < 8; j++) O[i][j] = 0.0f;
    }

    __syncthreads();

    for (int kt = kt0; kt <= t0; kt += 64) {
        // load K (d-major) and V (natural) tiles
#pragma unroll
        for (int it = 0; it < 8; it++) {
            int id = tid + it * 256;
            int r = id >> 5;
            int c4 = (id & 31) << 2;
            float4 kv = *(const float4*)(Kbase + (size_t)(kt + r) * HDIM + c4);
            Ks[(c4 + 0) * 68 + r] = kv.x;
            Ks[(c4 + 1) * 68 + r] = kv.y;
            Ks[(c4 + 2) * 68 + r] = kv.z;
            Ks[(c4 + 3) * 68 + r] = kv.w;
            float4 vv = *(const float4*)(Vbase + (size_t)(kt + r) * HDIM + c4);
            *(float4*)&Vs[r * HDIM + c4] = vv;
        }
        __syncthreads();

        // S = Q K^T  (4x4 per thread)
        float s[4][4];
#pragma unroll
        for (int i = 0; i < 4; i++)
#pragma unroll
            for (int j = 0; j < 4; j++) s[i][j] = 0.0f;

#pragma unroll 4
        for (int d = 0; d < HDIM; d++) {
            float4 a = *(float4*)&Qs[d * 68 + r0];
            float4 kb = *(float4*)&Ks[d * 68 + c0];
            float av[4] = {a.x, a.y, a.z, a.w};
            float bv[4] = {kb.x, kb.y, kb.z, kb.w};
#pragma unroll
            for (int i = 0; i < 4; i++)
#pragma unroll
                for (int j = 0; j < 4; j++)
                    s[i][j] = fmaf(av[i], bv[j], s[i][j]);
        }

        // mask + scale
#pragma unroll
        for (int i = 0; i < 4; i++) {
            int qi = t0 + r0 + i;
#pragma unroll
            for (int j = 0; j < 4; j++) {
                int kj = kt + c0 + j;
                bool ok = (kj <= qi) && (kj >= ds[i]);
                s[i][j] = ok ? s[i][j] * ATT_SCALE : -1.0e30f;
            }
        }

        // online softmax update per q-row
#pragma unroll
        for (int i = 0; i < 4; i++) {
            float mx = fmaxf(fmaxf(s[i][0], s[i][1]), fmaxf(s[i][2], s[i][3]));
#pragma unroll
            for (int off = 8; off >= 1; off >>= 1)
                mx = fmaxf(mx, __shfl_xor_sync(0xffffffffu, mx, off));
            float mnew = fmaxf(m[i], mx);
            float corr = __expf(m[i] - mnew);
            float p[4];
            float psum = 0.0f;
#pragma unroll
            for (int j = 0; j < 4; j++) {
                float pv = __expf(s[i][j] - mnew);
                if (s[i][j] < -1.0e29f) pv = 0.0f;
                p[j] = pv;
                psum += pv;
            }
#pragma unroll
            for (int off = 8; off >= 1; off >>= 1)
                psum += __shfl_xor_sync(0xffffffffu, psum, off);
            l[i] = l[i] * corr + psum;
            m[i] = mnew;
#pragma unroll
            for (int j = 0; j < 8; j++) O[i][j] *= corr;
            *(float4*)&Ps[(r0 + i) * 68 + c0] = make_float4(p[0], p[1], p[2], p[3]);
        }
        __syncthreads();

        // O += P @ V
#pragma unroll 2
        for (int c = 0; c < 64; c++) {
            float p0 = Ps[(r0 + 0) * 68 + c];
            float p1 = Ps[(r0 + 1) * 68 + c];
            float p2 = Ps[(r0 + 2) * 68 + c];
            float p3 = Ps[(r0 + 3) * 68 + c];
            float4 v0 = *(float4*)&Vs[c * HDIM + d0];
            float4 v1 = *(float4*)&Vs[c * HDIM + d0 + 4];
            float vv[8] = {v0.x, v0.y, v0.z, v0.w, v1.x, v1.y, v1.z, v1.w};
#pragma unroll
            for (int j = 0; j < 8; j++) {
                O[0][j] = fmaf(p0, vv[j], O[0][j]);
                O[1][j] = fmaf(p1, vv[j], O[1][j]);
                O[2][j] = fmaf(p2, vv[j], O[2][j]);
                O[3][j] = fmaf(p3, vv[j], O[3][j]);
            }
        }
        __syncthreads();
    }

    // normalize + write: out[b][t][h*128 + d]
#pragma unroll
    for (int i = 0; i < 4; i++) {
        float inv = 1.0f / l[i];
        float* orow = Out + ((size_t)b * SEQ + t0 + r0 + i) * DMODEL + h * HDIM + d0;
        *(float4*)orow =
            make_float4(O[i][0] * inv, O[i][1] * inv, O[i][2] * inv, O[i][3] * inv);
        *(float4*)(orow + 4) =
            make_float4(O[i][4] * inv, O[i][5] * inv, O[i][6] * inv, O[i][7] * inv);
    }
}

// ---------------------------------------------------------------------------
extern "C" void kernel_launch(void* const* d_in, const int* in_sizes, int n_in,
                              void* d_out, int out_size)
{
    const float* x    = (const float*)d_in[0];
    const float* sinp = (const float*)d_in[1];
    const float* cosp = (const float*)d_in[2];
    const int*   doc  = (const int*)d_in[3];
    const float* wqkv = (const float*)d_in[4];
    const float* wo   = (const float*)d_in[5];
    float* out = (float*)d_out;

    float *qkv, *q, *k, *v, *att;
    int* dstart;
    cudaGetSymbolAddress((void**)&qkv, g_qkv);
    cudaGetSymbolAddress((void**)&q, g_q);
    cudaGetSymbolAddress((void**)&k, g_k);
    cudaGetSymbolAddress((void**)&v, g_v);
    cudaGetSymbolAddress((void**)&att, g_att);
    cudaGetSymbolAddress((void**)&dstart, g_dstart);

    // 1) QKV projection: [4096,2048] @ [2048,3072]
    sgemm128<<<dim3(QKVN / 128, BT / 128), 256>>>(x, wqkv, qkv, BT, QKVN, DMODEL);

    // 2) RoPE + reorder
    rope_reorder<<<(BT * 1536) / 256, 256>>>(qkv, sinp, cosp, q, k, v);

    // 3) doc starts
    docstart_kernel<<<BT / 256, 256>>>(doc, dstart);

    // 4) flash attention
    cudaFuncSetAttribute(flash_kernel,
                         cudaFuncAttributeMaxDynamicSharedMemorySize,
                         FA_SMEM_BYTES);
    flash_kernel<<<dim3(SEQ / 64, NHEADS, BATCH), 256, FA_SMEM_BYTES>>>(
        q, k, v, dstart, att);

    // 5) output projection: [4096,2048] @ [2048,2048]
    sgemm128<<<dim3(DMODEL / 128, BT / 128), 256>>>(att, wo, out, BT, DMODEL, DMODEL);
}